// round 16
// baseline (speedup 1.0000x reference)
#include <cuda_runtime.h>

#define INDIM   256
#define OUTDIM  256
#define BATCH   128
#define NK      12                  // dense slots per input: 11 coef + 1 residual
#define KS      64                  // k-splits over inputs
#define IPC     (INDIM / KS)        // 4 inputs per chunk
#define KCH     (IPC * NK)          // 48 dense k per chunk
#define OT      128                 // output cols per block
#define TBB     64                  // batch rows per block
#define VSTR    132                 // padded s_V row stride (mult of 4 -> 16B-aligned LDS.128)
#define NTHR    256

#define SMEM_V  (KCH * VSTR)                    // 6336 f32 (25344 B)
#define SMEM_W  (KCH * TBB)                     // 3072 f32 (12288 B)
#define DYN_SMEM ((SMEM_V + SMEM_W) * 4)        // 37632 B

__device__ __forceinline__ unsigned long long pack2(float v)
{
    unsigned long long p;
    asm("mov.b64 %0, {%1, %1};" : "=l"(p) : "r"(__float_as_uint(v)));
    return p;
}

// ---- single fused kernel: fold + closed-form basis + split-K GEMM + REDG ----
__global__ __launch_bounds__(NTHR)
void kan_gemm(const float* __restrict__ x,
              const float* __restrict__ coef,
              const float* __restrict__ rw,
              const float* __restrict__ uw,
              float* __restrict__ out)
{
    extern __shared__ __align__(16) float dyn[];
    float* s_V = dyn;                // [k][o_l] stride VSTR
    float* s_W = dyn + SMEM_V;       // [k][b_l] stride TBB

    const int o0 = blockIdx.x * OT;
    const int b0 = blockIdx.y * TBB;
    const int ks = blockIdx.z;
    const int i0 = ks * IPC;
    const int t  = threadIdx.x;

    // ---- phase 0: zero s_W (scatter target) ---------------------------------
    {
        float4* sw4 = (float4*)s_W;
        const float4 z = make_float4(0.f, 0.f, 0.f, 0.f);
        #pragma unroll
        for (int q = t; q < SMEM_W / 4; q += NTHR) sw4[q] = z;   // 3 STS.128
    }

    // ---- phase 1: fold coef*uw and rw -> s_V (2 (o,i) pairs per thread) -----
    #pragma unroll
    for (int pp2 = 0; pp2 < 2; ++pp2) {
        const int p   = t + pp2 * NTHR;          // 0..511
        const int o_l = p >> 2, i_l = p & 3;
        const int gi  = (o0 + o_l) * INDIM + i0 + i_l;
        const float u = uw[gi];
        const float r = rw[gi];
        const float* c = coef + (size_t)(o0 + o_l) * (INDIM * 11) + (i0 + i_l) * 11;
        float* vb = &s_V[(i_l * NK) * VSTR + o_l];
        #pragma unroll
        for (int kk = 0; kk < 11; ++kk)
            vb[kk * VSTR] = u * c[kk];           // one-time STS, ~2-way conflicts
        vb[11 * VSTR] = r;
    }

    // ---- phase 2: closed-form uniform cubic basis, scatter into zeroed s_W --
    // knots: g[q] = -1.75 + 0.25 q  ->  u = 4x + 7, j = floor(u) in [3,10]
    {
        const int b_l  = t & 63;
        const int i_l  = t >> 6;                 // 0..3, one input each
        const float xv = x[(b0 + b_l) * INDIM + i0 + i_l];

        __syncthreads();                         // s_W zeroing done before scatter

        float u  = fmaf(xv, 4.0f, 7.0f);
        float fj = floorf(u);
        fj = fminf(fmaxf(fj, 3.0f), 10.0f);
        const float tt = u - fj;                 // [0,1)
        const int   j  = (int)fj;

        const float omt = 1.0f - tt;
        const float t2  = tt * tt;
        const float t3  = t2 * tt;
        const float k6  = 1.0f / 6.0f;
        const float w0 = omt * omt * omt * k6;
        const float w1 = fmaf(0.5f, t3, fmaf(-1.0f, t2, 4.0f * k6));
        const float w2 = fmaf(0.5f, t2 + tt - t3, k6);
        const float w3 = t3 * k6;
        const float si = xv / (1.0f + __expf(-xv));   // silu

        float* wb = &s_W[(i_l * NK) * TBB + b_l];
        const int idx = j - 3;                   // 0..7
        wb[(idx    ) * TBB] = w0;                // bank = b_l -> conflict-free scatter
        wb[(idx + 1) * TBB] = w1;
        wb[(idx + 2) * TBB] = w2;
        wb[(idx + 3) * TBB] = w3;
        wb[ 11       * TBB] = si;
    }
    __syncthreads();

    // ---- main loop: thread = (lane -> 4 o cols, warp -> 8 b-rows) -----------
    const int lane = t & 31;
    const int wrp  = t >> 5;                     // 0..7
    const int bb   = wrp * 8;

    // acc2[oi*4+j] = {out[b=bb+2j][o=o_l+oi], out[b=bb+2j+1][o=o_l+oi]}
    unsigned long long acc2[16];
    #pragma unroll
    for (int j = 0; j < 16; ++j) acc2[j] = 0ull;

    const float4* vp = (const float4*)&s_V[4 * lane];

    #pragma unroll 4
    for (int k = 0; k < KCH; ++k) {
        // per-lane distinct 4 o's: 512B/warp contiguous, conflict-free LDS.128
        const float4 v4 = vp[k * (VSTR / 4)];
        const unsigned long long vd[4] = {
            pack2(v4.x), pack2(v4.y), pack2(v4.z), pack2(v4.w) };

        const ulonglong2* wp2 = (const ulonglong2*)&s_W[k * TBB + bb];  // 32B-aligned
        ulonglong2 w01 = wp2[0];                 // LDS.128 (uniform addr)
        ulonglong2 w23 = wp2[1];

        #pragma unroll
        for (int oi = 0; oi < 4; ++oi) {
            asm("fma.rn.f32x2 %0, %1, %2, %0;" : "+l"(acc2[oi*4+0]) : "l"(w01.x), "l"(vd[oi]));
            asm("fma.rn.f32x2 %0, %1, %2, %0;" : "+l"(acc2[oi*4+1]) : "l"(w01.y), "l"(vd[oi]));
            asm("fma.rn.f32x2 %0, %1, %2, %0;" : "+l"(acc2[oi*4+2]) : "l"(w23.x), "l"(vd[oi]));
            asm("fma.rn.f32x2 %0, %1, %2, %0;" : "+l"(acc2[oi*4+3]) : "l"(w23.y), "l"(vd[oi]));
        }
    }

    // ---- split-K accumulate directly into out via no-return global atomics --
    const int ob = o0 + 4 * lane;
    #pragma unroll
    for (int oi = 0; oi < 4; ++oi) {
        #pragma unroll
        for (int j = 0; j < 4; ++j) {
            unsigned int lo, hi;
            asm("mov.b64 {%0, %1}, %2;" : "=r"(lo), "=r"(hi) : "l"(acc2[oi*4+j]));
            float* r0 = out + (size_t)(b0 + bb + 2*j    ) * OUTDIM + ob + oi;
            float* r1 = out + (size_t)(b0 + bb + 2*j + 1) * OUTDIM + ob + oi;
            asm volatile("red.global.add.f32 [%0], %1;" :: "l"(r0), "f"(__uint_as_float(lo)) : "memory");
            asm volatile("red.global.add.f32 [%0], %1;" :: "l"(r1), "f"(__uint_as_float(hi)) : "memory");
        }
    }
}

// ------------------------------------------------------------------------------
extern "C" void kernel_launch(void* const* d_in, const int* in_sizes, int n_in,
                              void* d_out, int out_size)
{
    const float* x    = (const float*)d_in[0];
    const float* coef = (const float*)d_in[2];
    const float* rw   = (const float*)d_in[3];
    const float* uw   = (const float*)d_in[4];

    cudaFuncSetAttribute(kan_gemm, cudaFuncAttributeMaxDynamicSharedMemorySize, DYN_SMEM);

    // zero the accumulator (memset node in the captured graph, then one kernel)
    cudaMemsetAsync(d_out, 0, (size_t)out_size * sizeof(float), 0);

    kan_gemm<<<dim3(OUTDIM / OT, BATCH / TBB, KS), NTHR, DYN_SMEM>>>(
        x, coef, rw, uw, (float*)d_out);
}

// round 17
// speedup vs baseline: 1.2614x; 1.2614x over previous
#include <cuda_runtime.h>

#define INDIM   256
#define OUTDIM  256
#define BATCH   128
#define NK      12                  // dense slots per input: 11 coef + 1 residual
#define KS      32                  // k-splits over inputs
#define IPC     (INDIM / KS)        // 8 inputs per chunk
#define KCH     (IPC * NK)          // 96 dense k per chunk
#define OT      64                  // output cols per block
#define TBB     64                  // batch rows per block
#define VSTR    66                  // padded s_V row stride (even -> 8B-aligned LDS.64)
#define NTHR    256

#define SMEM_V  (KCH * VSTR)                    // 6336 f32 (25344 B)
#define SMEM_W  (KCH * TBB)                     // 6144 f32 (24576 B)
#define DYN_SMEM ((SMEM_V + SMEM_W) * 4)        // 49920 B

__device__ __forceinline__ unsigned long long pack2(unsigned int v)
{
    unsigned long long p;
    asm("mov.b64 %0, {%1, %1};" : "=l"(p) : "r"(v));
    return p;
}

// ---- single fused kernel: fold + closed-form basis + split-K GEMM + REDG ----
__global__ __launch_bounds__(NTHR)
void kan_gemm(const float* __restrict__ x,
              const float* __restrict__ coef,
              const float* __restrict__ rw,
              const float* __restrict__ uw,
              float* __restrict__ out)
{
    extern __shared__ __align__(16) float dyn[];
    float* s_V = dyn;                // [k][o_l] stride VSTR
    float* s_W = dyn + SMEM_V;       // [k][b_l] stride TBB

    const int o0 = blockIdx.x * OT;
    const int b0 = blockIdx.y * TBB;
    const int ks = blockIdx.z;
    const int i0 = ks * IPC;
    const int t  = threadIdx.x;

    // prefetch x for phase 2 (LDG latency hides under phases 0/1)
    const int b_l  = t & 63;
    const int part = t >> 6;                     // 0..3, 2 inputs each
    const float2 xv2 = *(const float2*)(x + (b0 + b_l) * INDIM + i0 + part * 2);

    // ---- phase 0: zero s_W (scatter target) ---------------------------------
    {
        float4* sw4 = (float4*)s_W;
        const float4 z = make_float4(0.f, 0.f, 0.f, 0.f);
        #pragma unroll
        for (int q = t; q < SMEM_W / 4; q += NTHR) sw4[q] = z;   // 6 STS.128
    }

    // ---- phase 1: fold coef*uw and rw -> s_V (2 (o,i) pairs per thread) -----
    #pragma unroll
    for (int pp2 = 0; pp2 < 2; ++pp2) {
        const int p   = t + pp2 * NTHR;          // 0..511
        const int o_l = p >> 3, i_l = p & 7;
        const int gi  = (o0 + o_l) * INDIM + i0 + i_l;
        const float u = uw[gi];
        const float r = rw[gi];
        const float* c = coef + (size_t)(o0 + o_l) * (INDIM * 11) + (i0 + i_l) * 11;
        float* vb = &s_V[(i_l * NK) * VSTR + o_l];
        #pragma unroll
        for (int kk = 0; kk < 11; ++kk)
            vb[kk * VSTR] = u * c[kk];           // one-time STS, 2-way conflicts
        vb[11 * VSTR] = r;
    }

    __syncthreads();                             // s_W zeroing done before scatter

    // ---- phase 2: closed-form uniform cubic basis, scatter into zeroed s_W --
    // knots: g[q] = -1.75 + 0.25 q  ->  u = 4x + 7, j = floor(u) in [3,10]
    {
        #pragma unroll
        for (int s = 0; s < 2; ++s) {
            const float xv = (s == 0) ? xv2.x : xv2.y;
            float u  = fmaf(xv, 4.0f, 7.0f);
            float fj = floorf(u);
            fj = fminf(fmaxf(fj, 3.0f), 10.0f);
            const float tt = u - fj;             // [0,1)
            const int   j  = (int)fj;

            const float omt = 1.0f - tt;
            const float t2  = tt * tt;
            const float t3  = t2 * tt;
            const float k6  = 1.0f / 6.0f;
            const float w0 = omt * omt * omt * k6;
            const float w1 = fmaf(0.5f, t3, fmaf(-1.0f, t2, 4.0f * k6));
            const float w2 = fmaf(0.5f, t2 + tt - t3, k6);
            const float w3 = t3 * k6;
            const float si = xv / (1.0f + __expf(-xv));   // silu

            const int i_l = part * 2 + s;
            float* wb = &s_W[(i_l * NK) * TBB + b_l];
            const int idx = j - 3;               // 0..7
            wb[(idx    ) * TBB] = w0;            // bank = b_l -> conflict-free scatter
            wb[(idx + 1) * TBB] = w1;
            wb[(idx + 2) * TBB] = w2;
            wb[(idx + 3) * TBB] = w3;
            wb[ 11       * TBB] = si;
        }
    }
    __syncthreads();

    // ---- main loop: thread = (lane -> o-pair {2l,2l+1}, warp -> 8 b-rows) ---
    const int lane = t & 31;
    const int wrp  = t >> 5;                     // 0..7
    const int bb   = wrp * 8;

    unsigned long long accA[4] = {0ull, 0ull, 0ull, 0ull};  // o even
    unsigned long long accB[4] = {0ull, 0ull, 0ull, 0ull};  // o odd

    const float* vp = &s_V[2 * lane];

    #pragma unroll 8
    for (int k = 0; k < KCH; ++k) {
        // per-lane distinct o-pair: 256B/warp contiguous, conflict-free LDS.64
        const unsigned long long v01 = *(const unsigned long long*)(vp + k * VSTR);
        unsigned int lo, hi;
        asm("mov.b64 {%0, %1}, %2;" : "=r"(lo), "=r"(hi) : "l"(v01));
        const unsigned long long va = pack2(lo);
        const unsigned long long vb = pack2(hi);

        const ulonglong2* wp = (const ulonglong2*)&s_W[k * TBB + bb];  // 32B-aligned
        ulonglong2 w01 = wp[0];                  // LDS.128 (uniform addr)
        ulonglong2 w23 = wp[1];
        asm("fma.rn.f32x2 %0, %1, %2, %0;" : "+l"(accA[0]) : "l"(w01.x), "l"(va));
        asm("fma.rn.f32x2 %0, %1, %2, %0;" : "+l"(accA[1]) : "l"(w01.y), "l"(va));
        asm("fma.rn.f32x2 %0, %1, %2, %0;" : "+l"(accA[2]) : "l"(w23.x), "l"(va));
        asm("fma.rn.f32x2 %0, %1, %2, %0;" : "+l"(accA[3]) : "l"(w23.y), "l"(va));
        asm("fma.rn.f32x2 %0, %1, %2, %0;" : "+l"(accB[0]) : "l"(w01.x), "l"(vb));
        asm("fma.rn.f32x2 %0, %1, %2, %0;" : "+l"(accB[1]) : "l"(w01.y), "l"(vb));
        asm("fma.rn.f32x2 %0, %1, %2, %0;" : "+l"(accB[2]) : "l"(w23.x), "l"(vb));
        asm("fma.rn.f32x2 %0, %1, %2, %0;" : "+l"(accB[3]) : "l"(w23.y), "l"(vb));
    }

    // ---- split-K accumulate into out via vector no-return atomics (v2) ------
    // accA[j]={b=bb+2j(o even), b=bb+2j+1(o even)}, accB same for o odd:
    // per b-row the (o, o+1) pair is ADJACENT in memory -> red.v2.f32
    const int oe = o0 + 2 * lane;                // even o column, 8B-aligned
    float* __restrict__ pb = out + (size_t)(b0 + bb) * OUTDIM + oe;
    #pragma unroll
    for (int j = 0; j < 4; ++j) {
        unsigned int alo, ahi, blo, bhi;
        asm("mov.b64 {%0, %1}, %2;" : "=r"(alo), "=r"(ahi) : "l"(accA[j]));
        asm("mov.b64 {%0, %1}, %2;" : "=r"(blo), "=r"(bhi) : "l"(accB[j]));
        float* r0 = pb + (size_t)(2 * j)     * OUTDIM;     // b = bb+2j
        float* r1 = pb + (size_t)(2 * j + 1) * OUTDIM;     // b = bb+2j+1
        asm volatile("red.global.add.v2.f32 [%0], {%1, %2};"
                     :: "l"(r0), "f"(__uint_as_float(alo)), "f"(__uint_as_float(blo)) : "memory");
        asm volatile("red.global.add.v2.f32 [%0], {%1, %2};"
                     :: "l"(r1), "f"(__uint_as_float(ahi)), "f"(__uint_as_float(bhi)) : "memory");
    }
}

// ------------------------------------------------------------------------------
extern "C" void kernel_launch(void* const* d_in, const int* in_sizes, int n_in,
                              void* d_out, int out_size)
{
    const float* x    = (const float*)d_in[0];
    const float* coef = (const float*)d_in[2];
    const float* rw   = (const float*)d_in[3];
    const float* uw   = (const float*)d_in[4];

    cudaFuncSetAttribute(kan_gemm, cudaFuncAttributeMaxDynamicSharedMemorySize, DYN_SMEM);

    // zero the accumulator (memset node in the captured graph, then one kernel)
    cudaMemsetAsync(d_out, 0, (size_t)out_size * sizeof(float), 0);

    kan_gemm<<<dim3(OUTDIM / OT, BATCH / TBB, KS), NTHR, DYN_SMEM>>>(
        x, coef, rw, uw, (float*)d_out);
}